// round 13
// baseline (speedup 1.0000x reference)
#include <cuda_runtime.h>

// InvDiff: x[64, 4096, 256] fp32
//   d[b,l,f] = x[b,l+1,f] - x[b,l,f]                 (l in [0,4095))
//   y[b,l,f] = x[b,l+1,f] - x[b,0,f]  (l<4094), 0    (l==4094)
// Output = [d flat | y flat]. HBM-ceiling-bound (~6.5 TB/s, traffic at floor).
// This round: __stwt write-through stores (the one store policy never tested)
// on top of the best-known structure. .wt skips L2 write allocation entirely,
// freeing LTS bandwidth/capacity for the read-reuse stream; warp stores are
// full 512B-contiguous lines, the best case for direct streaming.

static constexpr int B   = 64;
static constexpr int L   = 4096;
static constexpr int F   = 256;
static constexpr int F4  = F / 4;         // 64 float4 per row
static constexpr int LD  = L - 1;         // 4095 output rows

__device__ __forceinline__ float4 ldg256(const float4* p) {
    float4 v;
    asm volatile("ld.global.nc.L2::256B.v4.f32 {%0,%1,%2,%3}, [%4];"
                 : "=f"(v.x), "=f"(v.y), "=f"(v.z), "=f"(v.w)
                 : "l"(p));
    return v;
}

__device__ __forceinline__ float4 sub4(float4 a, float4 b) {
    float4 r; r.x = a.x - b.x; r.y = a.y - b.y; r.z = a.z - b.z; r.w = a.w - b.w;
    return r;
}

__global__ __launch_bounds__(512)
void invdiff_kernel(const float4* __restrict__ x, float4* __restrict__ out) {
    const int f  = threadIdx.x;                                   // 0..63
    const int l0 = (blockIdx.y * blockDim.y + threadIdx.y) * 2;   // even row
    const int b  = blockIdx.z;
    if (l0 >= LD) return;

    const int baseIn = b * (L * F4);
    const int outIdx = b * (LD * F4) + l0 * F4 + f;
    const int D      = B * LD * F4;       // float4 count of d block

    const float4 x0 = __ldg(&x[baseIn + f]);   // 1KB/batch broadcast, cache-hot

    if (l0 + 2 < LD) {
        // Bulk path: no predication, 3 front-batched promoted loads.
        const float4 xa = ldg256(&x[baseIn +  l0      * F4 + f]);
        const float4 xb = ldg256(&x[baseIn + (l0 + 1) * F4 + f]);
        const float4 xc = ldg256(&x[baseIn + (l0 + 2) * F4 + f]);

        __stwt(&out[outIdx],          sub4(xb, xa));
        __stwt(&out[outIdx + F4],     sub4(xc, xb));
        __stwt(&out[D + outIdx],      sub4(xb, x0));
        __stwt(&out[D + outIdx + F4], sub4(xc, x0));
    } else {
        // Tail: rows near l = LD-1 (y's last row is zero; d may lack row 2).
        const float4 xa = __ldg(&x[baseIn + l0 * F4 + f]);
        const float4 xb = __ldg(&x[baseIn + (l0 + 1) * F4 + f]);

        __stwt(&out[outIdx], sub4(xb, xa));
        float4 y0;
        if (l0 < LD - 1) y0 = sub4(xb, x0);
        else { y0.x = 0.f; y0.y = 0.f; y0.z = 0.f; y0.w = 0.f; }
        __stwt(&out[D + outIdx], y0);

        if (l0 + 1 < LD) {
            const float4 xc = __ldg(&x[baseIn + (l0 + 2) * F4 + f]);
            __stwt(&out[outIdx + F4], sub4(xc, xb));
            float4 y1;
            if (l0 + 1 < LD - 1) y1 = sub4(xc, x0);
            else { y1.x = 0.f; y1.y = 0.f; y1.z = 0.f; y1.w = 0.f; }
            __stwt(&out[D + outIdx + F4], y1);
        }
    }
}

extern "C" void kernel_launch(void* const* d_in, const int* in_sizes, int n_in,
                              void* d_out, int out_size) {
    const float4* x = (const float4*)d_in[0];
    float4* out = (float4*)d_out;

    // 2048 l-pairs, 8 pairs per block in y -> 256 blocks in y
    dim3 block(F4, 8, 1);                            // 512 threads
    dim3 grid(1, (2048 + 7) / 8, B);                 // 256 x 64 blocks
    invdiff_kernel<<<grid, block>>>(x, out);
}

// round 14
// speedup vs baseline: 1.0048x; 1.0048x over previous
#include <cuda_runtime.h>

// InvDiff: x[64, 4096, 256] fp32
//   d[b,l,f] = x[b,l+1,f] - x[b,l,f]                 (l in [0,4095))
//   y[b,l,f] = x[b,l+1,f] - x[b,0,f]  (l<4094), 0    (l==4094)
// Output = [d flat | y flat].
//
// CONVERGED CHAMPION. HBM-ceiling-bound: traffic at the analytic floor
// (536MB mandatory writes + ~211MB L2-deduped reads) and eight structurally
// distinct variants (RPT 1/2/4, store policies default/.cs/.wt, load hints
// default/.nc/.nc.L2::256B, 128/256-bit vectors, d/y stream split,
// occupancy 59-82%, block 256/512) all measure 6.37-6.51 TB/s. The limiter
// is the HBM controller on the 1R:2W mix, not the SMs (issue ~10%).
// Best variant: RPT=2, L2::256B read promotion, 512-thread blocks,
// predication-free bulk path. ncu-stable at 114.8-115.1us.

static constexpr int B   = 64;
static constexpr int L   = 4096;
static constexpr int F   = 256;
static constexpr int F4  = F / 4;         // 64 float4 per row
static constexpr int LD  = L - 1;         // 4095 output rows

__device__ __forceinline__ float4 ldg256(const float4* p) {
    float4 v;
    asm volatile("ld.global.nc.L2::256B.v4.f32 {%0,%1,%2,%3}, [%4];"
                 : "=f"(v.x), "=f"(v.y), "=f"(v.z), "=f"(v.w)
                 : "l"(p));
    return v;
}

__device__ __forceinline__ float4 sub4(float4 a, float4 b) {
    float4 r; r.x = a.x - b.x; r.y = a.y - b.y; r.z = a.z - b.z; r.w = a.w - b.w;
    return r;
}

__global__ __launch_bounds__(512)
void invdiff_kernel(const float4* __restrict__ x, float4* __restrict__ out) {
    const int f  = threadIdx.x;                                   // 0..63
    const int l0 = (blockIdx.y * blockDim.y + threadIdx.y) * 2;   // even row
    const int b  = blockIdx.z;
    if (l0 >= LD) return;

    const int baseIn = b * (L * F4);
    const int outIdx = b * (LD * F4) + l0 * F4 + f;
    const int D      = B * LD * F4;       // float4 count of d block

    const float4 x0 = __ldg(&x[baseIn + f]);   // 1KB/batch broadcast, cache-hot

    if (l0 + 2 < LD) {
        // Bulk path: no predication, 3 front-batched promoted loads.
        const float4 xa = ldg256(&x[baseIn +  l0      * F4 + f]);
        const float4 xb = ldg256(&x[baseIn + (l0 + 1) * F4 + f]);
        const float4 xc = ldg256(&x[baseIn + (l0 + 2) * F4 + f]);

        out[outIdx]          = sub4(xb, xa);
        out[outIdx + F4]     = sub4(xc, xb);
        out[D + outIdx]      = sub4(xb, x0);
        out[D + outIdx + F4] = sub4(xc, x0);
    } else {
        // Tail: rows near l = LD-1 (y's last row is zero; d may lack row 2).
        const float4 xa = __ldg(&x[baseIn + l0 * F4 + f]);
        const float4 xb = __ldg(&x[baseIn + (l0 + 1) * F4 + f]);

        out[outIdx] = sub4(xb, xa);
        float4 y0;
        if (l0 < LD - 1) y0 = sub4(xb, x0);
        else { y0.x = 0.f; y0.y = 0.f; y0.z = 0.f; y0.w = 0.f; }
        out[D + outIdx] = y0;

        if (l0 + 1 < LD) {
            const float4 xc = __ldg(&x[baseIn + (l0 + 2) * F4 + f]);
            out[outIdx + F4] = sub4(xc, xb);
            float4 y1;
            if (l0 + 1 < LD - 1) y1 = sub4(xc, x0);
            else { y1.x = 0.f; y1.y = 0.f; y1.z = 0.f; y1.w = 0.f; }
            out[D + outIdx + F4] = y1;
        }
    }
}

extern "C" void kernel_launch(void* const* d_in, const int* in_sizes, int n_in,
                              void* d_out, int out_size) {
    const float4* x = (const float4*)d_in[0];
    float4* out = (float4*)d_out;

    // 2048 l-pairs, 8 pairs per block in y -> 256 blocks in y
    dim3 block(F4, 8, 1);                            // 512 threads
    dim3 grid(1, (2048 + 7) / 8, B);                 // 256 x 64 blocks
    invdiff_kernel<<<grid, block>>>(x, out);
}

// round 15
// speedup vs baseline: 1.0145x; 1.0097x over previous
#include <cuda_runtime.h>

// InvDiff: x[64, 4096, 256] fp32
//   d[b,l,f] = x[b,l+1,f] - x[b,l,f]                 (l in [0,4095))
//   y[b,l,f] = x[b,l+1,f] - x[b,0,f]  (l<4094), 0    (l==4094)
// Output = [d flat | y flat].
//
// CONVERGED CHAMPION (5 confirming ncu runs: 114.8-115.7us, 6.46-6.51 TB/s).
// HBM-ceiling-bound: traffic at the analytic floor (536MB mandatory writes +
// ~211MB L2-deduped reads); eight structurally distinct variants across every
// axis (RPT 1/2/4, store policies default/.cs/.wt, load hints default/.nc/
// .nc.L2::256B, 128/256-bit vectors, d/y stream split, occupancy 59-82%,
// block 256/512) all land at 6.37-6.51 TB/s. Limiter: HBM controller on the
// 1R:2W stream mix (~81% of spec = this workload's roofline); SMs idle
// (issue ~10%). Structure: RPT=2, L2::256B read promotion, 512-thread
// blocks, predication-free bulk path, closed-form y = x[l+1] - x[0]
// (telescoped cumsum; rel_err 1.7e-6).

static constexpr int B   = 64;
static constexpr int L   = 4096;
static constexpr int F   = 256;
static constexpr int F4  = F / 4;         // 64 float4 per row
static constexpr int LD  = L - 1;         // 4095 output rows

__device__ __forceinline__ float4 ldg256(const float4* p) {
    float4 v;
    asm volatile("ld.global.nc.L2::256B.v4.f32 {%0,%1,%2,%3}, [%4];"
                 : "=f"(v.x), "=f"(v.y), "=f"(v.z), "=f"(v.w)
                 : "l"(p));
    return v;
}

__device__ __forceinline__ float4 sub4(float4 a, float4 b) {
    float4 r; r.x = a.x - b.x; r.y = a.y - b.y; r.z = a.z - b.z; r.w = a.w - b.w;
    return r;
}

__global__ __launch_bounds__(512)
void invdiff_kernel(const float4* __restrict__ x, float4* __restrict__ out) {
    const int f  = threadIdx.x;                                   // 0..63
    const int l0 = (blockIdx.y * blockDim.y + threadIdx.y) * 2;   // even row
    const int b  = blockIdx.z;
    if (l0 >= LD) return;

    const int baseIn = b * (L * F4);
    const int outIdx = b * (LD * F4) + l0 * F4 + f;
    const int D      = B * LD * F4;       // float4 count of d block

    const float4 x0 = __ldg(&x[baseIn + f]);   // 1KB/batch broadcast, cache-hot

    if (l0 + 2 < LD) {
        // Bulk path: no predication, 3 front-batched promoted loads.
        const float4 xa = ldg256(&x[baseIn +  l0      * F4 + f]);
        const float4 xb = ldg256(&x[baseIn + (l0 + 1) * F4 + f]);
        const float4 xc = ldg256(&x[baseIn + (l0 + 2) * F4 + f]);

        out[outIdx]          = sub4(xb, xa);
        out[outIdx + F4]     = sub4(xc, xb);
        out[D + outIdx]      = sub4(xb, x0);
        out[D + outIdx + F4] = sub4(xc, x0);
    } else {
        // Tail: rows near l = LD-1 (y's last row is zero; d may lack row 2).
        const float4 xa = __ldg(&x[baseIn + l0 * F4 + f]);
        const float4 xb = __ldg(&x[baseIn + (l0 + 1) * F4 + f]);

        out[outIdx] = sub4(xb, xa);
        float4 y0;
        if (l0 < LD - 1) y0 = sub4(xb, x0);
        else { y0.x = 0.f; y0.y = 0.f; y0.z = 0.f; y0.w = 0.f; }
        out[D + outIdx] = y0;

        if (l0 + 1 < LD) {
            const float4 xc = __ldg(&x[baseIn + (l0 + 2) * F4 + f]);
            out[outIdx + F4] = sub4(xc, xb);
            float4 y1;
            if (l0 + 1 < LD - 1) y1 = sub4(xc, x0);
            else { y1.x = 0.f; y1.y = 0.f; y1.z = 0.f; y1.w = 0.f; }
            out[D + outIdx + F4] = y1;
        }
    }
}

extern "C" void kernel_launch(void* const* d_in, const int* in_sizes, int n_in,
                              void* d_out, int out_size) {
    const float4* x = (const float4*)d_in[0];
    float4* out = (float4*)d_out;

    // 2048 l-pairs, 8 pairs per block in y -> 256 blocks in y
    dim3 block(F4, 8, 1);                            // 512 threads
    dim3 grid(1, (2048 + 7) / 8, B);                 // 256 x 64 blocks
    invdiff_kernel<<<grid, block>>>(x, out);
}